// round 5
// baseline (speedup 1.0000x reference)
#include <cuda_runtime.h>
#include <cuda_bf16.h>
#include <math.h>
#include <stdint.h>

#define T_TOK 4096
#define H_DIM 2048
#define I_DIM 2048
#define E_NUM 16

#define BM 128
#define BN 128
#define KC 32
#define PITCH 80                      // bytes per smem row (32 bf16 + pad)
#define TILE_B (BM * PITCH)           // 10240 bytes per tile
#define STAGE_B (4 * TILE_B)          // Ahi|Alo|Bhi|Blo = 40960
#define DYN_SMEM (2 * STAGE_B)        // 81920

#define MAX_SLOTS (T_TOK * 2 + E_NUM * BM)   // 10240
#define M_TILES   (MAX_SLOTS / BM)           // 80

// ---------------- scratch ---------------------------------------------------
__device__ int   g_slot_token[MAX_SLOTS];
__device__ int   g_tile_expert[M_TILES];
__device__ int   g_counts[E_NUM];
__device__ int   g_cursor[E_NUM];
__device__ int   g_seg_start[E_NUM];
__device__ int   g_tok_eid[T_TOK * 2];
__device__ int   g_tok_slot[T_TOK * 2];
__device__ float g_tok_w[T_TOK * 2];

__device__ float g_gu[(size_t)MAX_SLOTS * (2 * I_DIM)];
__device__ float g_h [(size_t)MAX_SLOTS * I_DIM];
__device__ float g_y [(size_t)MAX_SLOTS * H_DIM];

// ---------------- helpers ---------------------------------------------------
__device__ __forceinline__ uint32_t smem_u32(const void* p) {
    uint32_t a;
    asm("{ .reg .u64 t; cvta.to.shared.u64 t, %1; cvt.u32.u64 %0, t; }" : "=r"(a) : "l"(p));
    return a;
}

#define LDSM4(R, A)                                                             \
    asm volatile("ldmatrix.sync.aligned.m8n8.x4.shared.b16 {%0,%1,%2,%3}, [%4];" \
        : "=r"((R)[0]), "=r"((R)[1]), "=r"((R)[2]), "=r"((R)[3]) : "r"(A))

__device__ __forceinline__ void mma_bf16(float* d, const uint32_t* a, const uint32_t* b) {
    asm volatile("mma.sync.aligned.m16n8k16.row.col.f32.bf16.bf16.f32 "
        "{%0,%1,%2,%3}, {%4,%5,%6,%7}, {%8,%9}, {%0,%1,%2,%3};"
        : "+f"(d[0]), "+f"(d[1]), "+f"(d[2]), "+f"(d[3])
        : "r"(a[0]), "r"(a[1]), "r"(a[2]), "r"(a[3]), "r"(b[0]), "r"(b[1]));
}

// fp32x4 -> bf16 hi (8B) + bf16 lo (8B), pitched smem store
__device__ __forceinline__ void cvt_store(char* hi_t, char* lo_t, int row, int colf, float4 v) {
    __nv_bfloat162 h01 = __floats2bfloat162_rn(v.x, v.y);
    __nv_bfloat162 h23 = __floats2bfloat162_rn(v.z, v.w);
    float rx = v.x - __bfloat162float(h01.x);
    float ry = v.y - __bfloat162float(h01.y);
    float rz = v.z - __bfloat162float(h23.x);
    float rw = v.w - __bfloat162float(h23.y);
    __nv_bfloat162 l01 = __floats2bfloat162_rn(rx, ry);
    __nv_bfloat162 l23 = __floats2bfloat162_rn(rz, rw);
    uint32_t off = (uint32_t)(row * PITCH + colf * 2);
    *(uint2*)(hi_t + off) = make_uint2(*reinterpret_cast<uint32_t*>(&h01),
                                       *reinterpret_cast<uint32_t*>(&h23));
    *(uint2*)(lo_t + off) = make_uint2(*reinterpret_cast<uint32_t*>(&l01),
                                       *reinterpret_cast<uint32_t*>(&l23));
}

// ---------------- routing / bookkeeping -------------------------------------
__global__ void k_init() {
    int i = blockIdx.x * blockDim.x + threadIdx.x;
    if (i < MAX_SLOTS) g_slot_token[i] = -1;
    if (i < E_NUM) { g_counts[i] = 0; g_cursor[i] = 0; }
}

__global__ void __launch_bounds__(512) k_route(const float* __restrict__ x,
                                               const float* __restrict__ gw) {
    int t = blockIdx.x, warp = threadIdx.x >> 5, lane = threadIdx.x & 31;
    const float* xr = x + (size_t)t * H_DIM;
    const float* gr = gw + (size_t)warp * H_DIM;
    float s = 0.f;
    for (int k = lane; k < H_DIM; k += 32) s += xr[k] * gr[k];
    #pragma unroll
    for (int o = 16; o; o >>= 1) s += __shfl_xor_sync(0xffffffffu, s, o);
    __shared__ float logits[E_NUM];
    if (lane == 0) logits[warp] = s;
    __syncthreads();
    if (threadIdx.x == 0) {
        int i0 = -1, i1 = -1; float v0 = -1e30f, v1 = -1e30f;
        #pragma unroll
        for (int e = 0; e < E_NUM; e++) {
            float v = logits[e];
            if (v > v0) { v1 = v0; i1 = i0; v0 = v; i0 = e; }
            else if (v > v1) { v1 = v; i1 = e; }
        }
        float e1 = expf(v1 - v0);
        float w0 = 1.f / (1.f + e1);
        g_tok_eid[t * 2 + 0] = i0;  g_tok_eid[t * 2 + 1] = i1;
        g_tok_w [t * 2 + 0] = w0;  g_tok_w [t * 2 + 1] = e1 * w0;
        atomicAdd(&g_counts[i0], 1);
        atomicAdd(&g_counts[i1], 1);
    }
}

__global__ void k_offsets() {
    if (threadIdx.x == 0 && blockIdx.x == 0) {
        int run = 0;
        for (int e = 0; e < E_NUM; e++) {
            g_seg_start[e] = run;
            int padded = (g_counts[e] + BM - 1) / BM * BM;
            for (int tt = run / BM; tt < (run + padded) / BM; tt++) g_tile_expert[tt] = e;
            run += padded;
        }
        for (int tt = run / BM; tt < M_TILES; tt++) g_tile_expert[tt] = 0;
    }
}

__global__ void k_scatter() {
    int t = blockIdx.x * blockDim.x + threadIdx.x;
    if (t >= T_TOK) return;
    #pragma unroll
    for (int k = 0; k < 2; k++) {
        int e = g_tok_eid[t * 2 + k];
        int pos = atomicAdd(&g_cursor[e], 1);
        int slot = g_seg_start[e] + pos;
        g_slot_token[slot] = t;
        g_tok_slot[t * 2 + k] = slot;
    }
}

// ---------------- bf16-split tensor-core GEMM, double-buffered --------------
// MODE 0: gather(x)[slot] @ ws[e]^T  (K=2048, NT=4096) -> g_gu
// MODE 1: g_h[slot]       @ w2s[e]^T (K=2048, NT=2048) -> g_y
template <int MODE>
__global__ void __launch_bounds__(256, 1) k_gemm_tc(const float* __restrict__ X,
                                                    const float* __restrict__ Wall) {
    constexpr int K  = 2048;
    constexpr int NT = (MODE == 0) ? 4096 : 2048;
    constexpr int NCH = K / KC;
    float* __restrict__ C = (MODE == 0) ? g_gu : g_y;

    const int mt = blockIdx.y, nt = blockIdx.x;
    const int expert = g_tile_expert[mt];
    const float* __restrict__ Wb = Wall + (size_t)expert * NT * K;

    extern __shared__ __align__(128) char sm[];   // [2][Ahi|Alo|Bhi|Blo]

    const int tid  = threadIdx.x;
    const int lane = tid & 31;
    const int wid  = tid >> 5;
    const int wm   = wid & 1;          // 2 warps along M (64 rows each)
    const int wn   = wid >> 1;         // 4 warps along N (32 cols each)

    const int lrow = tid >> 1;
    const int lhal = tid & 1;

    const float* arow;
    if (MODE == 0) {
        int tok = g_slot_token[mt * BM + lrow];
        arow = (tok >= 0) ? (X + (size_t)tok * K) : (const float*)0;
    } else {
        arow = g_h + (size_t)(mt * BM + lrow) * K;
    }
    const float* brow = Wb + (size_t)(nt * BN + lrow) * K;

    float acc[4][4][4];
    #pragma unroll
    for (int i = 0; i < 4; i++)
        #pragma unroll
        for (int j = 0; j < 4; j++)
            #pragma unroll
            for (int q = 0; q < 4; q++) acc[i][j][q] = 0.f;

    // prologue: chunk 0 -> buffer 0
    float4 pa[4], pb[4];
    #pragma unroll
    for (int i = 0; i < 4; i++) {
        pa[i] = arow ? *(const float4*)(arow + lhal * 16 + i * 4)
                     : make_float4(0.f, 0.f, 0.f, 0.f);
        pb[i] = *(const float4*)(brow + lhal * 16 + i * 4);
    }
    #pragma unroll
    for (int i = 0; i < 4; i++) {
        cvt_store(sm,              sm + TILE_B,     lrow, lhal * 16 + i * 4, pa[i]);
        cvt_store(sm + 2 * TILE_B, sm + 3 * TILE_B, lrow, lhal * 16 + i * 4, pb[i]);
    }
    __syncthreads();

    const uint32_t uBase = smem_u32(sm);

    for (int ic = 0; ic < NCH; ic++) {
        const uint32_t cur = uBase + (uint32_t)((ic & 1) * STAGE_B);
        char* nxt = sm + ((ic + 1) & 1) * STAGE_B;

        // issue global loads for next chunk (in flight under the MMAs)
        if (ic + 1 < NCH) {
            const int kb = (ic + 1) * KC;
            #pragma unroll
            for (int i = 0; i < 4; i++) {
                pa[i] = arow ? *(const float4*)(arow + kb + lhal * 16 + i * 4)
                             : make_float4(0.f, 0.f, 0.f, 0.f);
                pb[i] = *(const float4*)(brow + kb + lhal * 16 + i * 4);
            }
        }

        // compute on current buffer
        #pragma unroll
        for (int k16 = 0; k16 < 2; k16++) {
            uint32_t ahi[4][4], alo[4][4];
            #pragma unroll
            for (int i = 0; i < 4; i++) {
                uint32_t ad = cur + (uint32_t)((wm * 64 + i * 16 + (lane & 15)) * PITCH
                                               + k16 * 32 + (lane >> 4) * 16);
                LDSM4(ahi[i], ad);
                LDSM4(alo[i], ad + TILE_B);
            }
            uint32_t bhi[8], blo[8];
            #pragma unroll
            for (int p = 0; p < 2; p++) {
                uint32_t bd = cur + (uint32_t)(2 * TILE_B)
                            + (uint32_t)((wn * 32 + p * 16 + (lane & 7) + ((lane >> 4) << 3)) * PITCH
                                         + k16 * 32 + ((lane >> 3) & 1) * 16);
                LDSM4(&bhi[p * 4], bd);
                LDSM4(&blo[p * 4], bd + TILE_B);
            }
            #pragma unroll
            for (int i = 0; i < 4; i++)
                #pragma unroll
                for (int j = 0; j < 4; j++) {
                    const uint32_t* bh = &bhi[(j >> 1) * 4 + (j & 1) * 2];
                    const uint32_t* bl = &blo[(j >> 1) * 4 + (j & 1) * 2];
                    mma_bf16(acc[i][j], ahi[i], bh);
                    mma_bf16(acc[i][j], ahi[i], bl);
                    mma_bf16(acc[i][j], alo[i], bh);
                }
        }

        // stage next chunk into the other buffer, one barrier per chunk
        if (ic + 1 < NCH) {
            #pragma unroll
            for (int i = 0; i < 4; i++) {
                cvt_store(nxt,              nxt + TILE_B,     lrow, lhal * 16 + i * 4, pa[i]);
                cvt_store(nxt + 2 * TILE_B, nxt + 3 * TILE_B, lrow, lhal * 16 + i * 4, pb[i]);
            }
            __syncthreads();
        }
    }

    // epilogue
    const int mrow = mt * BM + wm * 64;
    const int ncol = nt * BN + wn * 32;
    #pragma unroll
    for (int i = 0; i < 4; i++) {
        int r0 = mrow + i * 16 + (lane >> 2);
        #pragma unroll
        for (int j = 0; j < 4; j++) {
            int c0 = ncol + j * 8 + 2 * (lane & 3);
            float* p0 = C + (size_t)r0 * NT + c0;
            p0[0] = acc[i][j][0];
            p0[1] = acc[i][j][1];
            float* p1 = p0 + (size_t)8 * NT;
            p1[0] = acc[i][j][2];
            p1[1] = acc[i][j][3];
        }
    }
}

// ---------------- silu(g) * u ----------------------------------------------
__global__ void k_act() {
    size_t idx = (size_t)blockIdx.x * blockDim.x + threadIdx.x;
    size_t total = (size_t)MAX_SLOTS * (I_DIM / 4);
    if (idx >= total) return;
    size_t slot = idx / (I_DIM / 4);
    int    i    = (int)(idx % (I_DIM / 4)) * 4;
    const float4 g = *(const float4*)&g_gu[slot * (2 * I_DIM) + i];
    const float4 u = *(const float4*)&g_gu[slot * (2 * I_DIM) + I_DIM + i];
    float4 h;
    h.x = g.x / (1.f + __expf(-g.x)) * u.x;
    h.y = g.y / (1.f + __expf(-g.y)) * u.y;
    h.z = g.z / (1.f + __expf(-g.z)) * u.z;
    h.w = g.w / (1.f + __expf(-g.w)) * u.w;
    *(float4*)&g_h[slot * I_DIM + i] = h;
}

// ---------------- combine ---------------------------------------------------
__global__ void k_combine(float* __restrict__ out) {
    int idx = blockIdx.x * blockDim.x + threadIdx.x;
    if (idx >= T_TOK * (H_DIM / 4)) return;
    int t = idx / (H_DIM / 4);
    int n = (idx % (H_DIM / 4)) * 4;
    int   s0 = g_tok_slot[t * 2 + 0], s1 = g_tok_slot[t * 2 + 1];
    float w0 = g_tok_w [t * 2 + 0], w1 = g_tok_w [t * 2 + 1];
    const float4 y0 = *(const float4*)&g_y[(size_t)s0 * H_DIM + n];
    const float4 y1 = *(const float4*)&g_y[(size_t)s1 * H_DIM + n];
    float4 o;
    o.x = w0 * y0.x + w1 * y1.x;
    o.y = w0 * y0.y + w1 * y1.y;
    o.z = w0 * y0.z + w1 * y1.z;
    o.w = w0 * y0.w + w1 * y1.w;
    *(float4*)&out[(size_t)t * H_DIM + n] = o;
}

// ---------------- launch ----------------------------------------------------
extern "C" void kernel_launch(void* const* d_in, const int* in_sizes, int n_in,
                              void* d_out, int out_size) {
    const float* x      = (const float*)d_in[0];
    const float* gate_w = (const float*)d_in[1];
    const float* ws     = (const float*)d_in[2];
    const float* w2s    = (const float*)d_in[3];
    float* out = (float*)d_out;

    cudaFuncSetAttribute(k_gemm_tc<0>, cudaFuncAttributeMaxDynamicSharedMemorySize, DYN_SMEM);
    cudaFuncSetAttribute(k_gemm_tc<1>, cudaFuncAttributeMaxDynamicSharedMemorySize, DYN_SMEM);

    k_init<<<(MAX_SLOTS + 255) / 256, 256>>>();
    k_route<<<T_TOK, 512>>>(x, gate_w);
    k_offsets<<<1, 32>>>();
    k_scatter<<<(T_TOK + 255) / 256, 256>>>();

    k_gemm_tc<0><<<dim3((2 * I_DIM) / BN, M_TILES), 256, DYN_SMEM>>>(x, ws);
    k_act<<<(int)(((size_t)MAX_SLOTS * (I_DIM / 4) + 255) / 256), 256>>>();
    k_gemm_tc<1><<<dim3(H_DIM / BN, M_TILES), 256, DYN_SMEM>>>(x, w2s);
    k_combine<<<(T_TOK * (H_DIM / 4) + 255) / 256, 256>>>(out);
}

// round 6
// speedup vs baseline: 1.0809x; 1.0809x over previous
#include <cuda_runtime.h>
#include <cuda_bf16.h>
#include <math.h>
#include <stdint.h>

#define T_TOK 4096
#define H_DIM 2048
#define I_DIM 2048
#define E_NUM 16

#define BM 128
#define BN 128
#define KC 32
#define PITCH 80                      // bytes per smem row (32 bf16 + pad)
#define TILE_B (BM * PITCH)           // 10240
#define STAGE_B (4 * TILE_B)          // Ahi|Alo|Bhi|Blo = 40960
#define STASH_B (256 * 64 * 4)        // 65536 (per-thread gate stash)
#define DYN1 (STAGE_B + STASH_B)      // 106496

#define MAX_SLOTS (T_TOK * 2 + E_NUM * BM)   // 10240
#define M_TILES   (MAX_SLOTS / BM)           // 80

// ---------------- scratch ---------------------------------------------------
__device__ int   g_slot_token[MAX_SLOTS];
__device__ int   g_tile_expert[M_TILES];
__device__ int   g_counts[E_NUM];
__device__ int   g_cursor[E_NUM];
__device__ int   g_seg_start[E_NUM];
__device__ int   g_tok_eid[T_TOK * 2];
__device__ int   g_tok_slot[T_TOK * 2];
__device__ float g_tok_w[T_TOK * 2];

__device__ float g_h[(size_t)MAX_SLOTS * I_DIM];
__device__ float g_y[(size_t)MAX_SLOTS * H_DIM];

// ---------------- helpers ---------------------------------------------------
__device__ __forceinline__ uint32_t smem_u32(const void* p) {
    uint32_t a;
    asm("{ .reg .u64 t; cvta.to.shared.u64 t, %1; cvt.u32.u64 %0, t; }" : "=r"(a) : "l"(p));
    return a;
}

#define LDSM4(R, A)                                                             \
    asm volatile("ldmatrix.sync.aligned.m8n8.x4.shared.b16 {%0,%1,%2,%3}, [%4];" \
        : "=r"((R)[0]), "=r"((R)[1]), "=r"((R)[2]), "=r"((R)[3]) : "r"(A))

__device__ __forceinline__ void mma_bf16(float* d, const uint32_t* a, const uint32_t* b) {
    asm volatile("mma.sync.aligned.m16n8k16.row.col.f32.bf16.bf16.f32 "
        "{%0,%1,%2,%3}, {%4,%5,%6,%7}, {%8,%9}, {%0,%1,%2,%3};"
        : "+f"(d[0]), "+f"(d[1]), "+f"(d[2]), "+f"(d[3])
        : "r"(a[0]), "r"(a[1]), "r"(a[2]), "r"(a[3]), "r"(b[0]), "r"(b[1]));
}

__device__ __forceinline__ void cvt_store(char* hi_t, char* lo_t, int row, int colf, float4 v) {
    __nv_bfloat162 h01 = __floats2bfloat162_rn(v.x, v.y);
    __nv_bfloat162 h23 = __floats2bfloat162_rn(v.z, v.w);
    float rx = v.x - __bfloat162float(h01.x);
    float ry = v.y - __bfloat162float(h01.y);
    float rz = v.z - __bfloat162float(h23.x);
    float rw = v.w - __bfloat162float(h23.y);
    __nv_bfloat162 l01 = __floats2bfloat162_rn(rx, ry);
    __nv_bfloat162 l23 = __floats2bfloat162_rn(rz, rw);
    uint32_t off = (uint32_t)(row * PITCH + colf * 2);
    *(uint2*)(hi_t + off) = make_uint2(*reinterpret_cast<uint32_t*>(&h01),
                                       *reinterpret_cast<uint32_t*>(&h23));
    *(uint2*)(lo_t + off) = make_uint2(*reinterpret_cast<uint32_t*>(&l01),
                                       *reinterpret_cast<uint32_t*>(&l23));
}

// ---------------- routing / bookkeeping -------------------------------------
__global__ void k_init() {
    int i = blockIdx.x * blockDim.x + threadIdx.x;
    if (i < MAX_SLOTS) g_slot_token[i] = -1;
    if (i < E_NUM) { g_counts[i] = 0; g_cursor[i] = 0; }
}

__global__ void __launch_bounds__(512) k_route(const float* __restrict__ x,
                                               const float* __restrict__ gw) {
    int t = blockIdx.x, warp = threadIdx.x >> 5, lane = threadIdx.x & 31;
    const float* xr = x + (size_t)t * H_DIM;
    const float* gr = gw + (size_t)warp * H_DIM;
    float s = 0.f;
    for (int k = lane; k < H_DIM; k += 32) s += xr[k] * gr[k];
    #pragma unroll
    for (int o = 16; o; o >>= 1) s += __shfl_xor_sync(0xffffffffu, s, o);
    __shared__ float logits[E_NUM];
    if (lane == 0) logits[warp] = s;
    __syncthreads();
    if (threadIdx.x == 0) {
        int i0 = -1, i1 = -1; float v0 = -1e30f, v1 = -1e30f;
        #pragma unroll
        for (int e = 0; e < E_NUM; e++) {
            float v = logits[e];
            if (v > v0) { v1 = v0; i1 = i0; v0 = v; i0 = e; }
            else if (v > v1) { v1 = v; i1 = e; }
        }
        float e1 = expf(v1 - v0);
        float w0 = 1.f / (1.f + e1);
        g_tok_eid[t * 2 + 0] = i0;  g_tok_eid[t * 2 + 1] = i1;
        g_tok_w [t * 2 + 0] = w0;  g_tok_w [t * 2 + 1] = e1 * w0;
        atomicAdd(&g_counts[i0], 1);
        atomicAdd(&g_counts[i1], 1);
    }
}

__global__ void k_offsets() {
    if (threadIdx.x == 0 && blockIdx.x == 0) {
        int run = 0;
        for (int e = 0; e < E_NUM; e++) {
            g_seg_start[e] = run;
            int padded = (g_counts[e] + BM - 1) / BM * BM;
            for (int tt = run / BM; tt < (run + padded) / BM; tt++) g_tile_expert[tt] = e;
            run += padded;
        }
        for (int tt = run / BM; tt < M_TILES; tt++) g_tile_expert[tt] = -1;  // dead tiles
    }
}

__global__ void k_scatter() {
    int t = blockIdx.x * blockDim.x + threadIdx.x;
    if (t >= T_TOK) return;
    #pragma unroll
    for (int k = 0; k < 2; k++) {
        int e = g_tok_eid[t * 2 + k];
        int pos = atomicAdd(&g_cursor[e], 1);
        int slot = g_seg_start[e] + pos;
        g_slot_token[slot] = t;
        g_tok_slot[t * 2 + k] = slot;
    }
}

// ---------------- shared mainloop: one K-pass of 128x128 bf16-split ---------
template <int K>
__device__ __forceinline__ void gemm_pass(const float* arow, const float* brow,
                                          char* sm, uint32_t uBase,
                                          int lrow, int lhal, int wm, int wn, int lane,
                                          float acc[4][4][4]) {
    constexpr int NCH = K / KC;
    float4 pa[4], pb[4];
    #pragma unroll
    for (int i = 0; i < 4; i++) {
        pa[i] = arow ? *(const float4*)(arow + lhal * 16 + i * 4)
                     : make_float4(0.f, 0.f, 0.f, 0.f);
        pb[i] = *(const float4*)(brow + lhal * 16 + i * 4);
    }
    #pragma unroll
    for (int i = 0; i < 4; i++) {
        cvt_store(sm,              sm + TILE_B,     lrow, lhal * 16 + i * 4, pa[i]);
        cvt_store(sm + 2 * TILE_B, sm + 3 * TILE_B, lrow, lhal * 16 + i * 4, pb[i]);
    }
    __syncthreads();

    for (int ic = 0; ic < NCH; ic++) {
        if (ic + 1 < NCH) {
            const int kb = (ic + 1) * KC;
            #pragma unroll
            for (int i = 0; i < 4; i++) {
                pa[i] = arow ? *(const float4*)(arow + kb + lhal * 16 + i * 4)
                             : make_float4(0.f, 0.f, 0.f, 0.f);
                pb[i] = *(const float4*)(brow + kb + lhal * 16 + i * 4);
            }
        }
        #pragma unroll
        for (int k16 = 0; k16 < 2; k16++) {
            uint32_t ahi[4][4], alo[4][4];
            #pragma unroll
            for (int i = 0; i < 4; i++) {
                uint32_t ad = uBase + (uint32_t)((wm * 64 + i * 16 + (lane & 15)) * PITCH
                                                 + k16 * 32 + (lane >> 4) * 16);
                LDSM4(ahi[i], ad);
                LDSM4(alo[i], ad + TILE_B);
            }
            uint32_t bhi[8], blo[8];
            #pragma unroll
            for (int p = 0; p < 2; p++) {
                uint32_t bd = uBase + (uint32_t)(2 * TILE_B)
                            + (uint32_t)((wn * 32 + p * 16 + (lane & 7) + ((lane >> 4) << 3)) * PITCH
                                         + k16 * 32 + ((lane >> 3) & 1) * 16);
                LDSM4(&bhi[p * 4], bd);
                LDSM4(&blo[p * 4], bd + TILE_B);
            }
            #pragma unroll
            for (int i = 0; i < 4; i++)
                #pragma unroll
                for (int j = 0; j < 4; j++) {
                    const uint32_t* bh = &bhi[(j >> 1) * 4 + (j & 1) * 2];
                    const uint32_t* bl = &blo[(j >> 1) * 4 + (j & 1) * 2];
                    mma_bf16(acc[i][j], ahi[i], bh);
                    mma_bf16(acc[i][j], ahi[i], bl);
                    mma_bf16(acc[i][j], alo[i], bh);
                }
        }
        __syncthreads();
        if (ic + 1 < NCH) {
            #pragma unroll
            for (int i = 0; i < 4; i++) {
                cvt_store(sm,              sm + TILE_B,     lrow, lhal * 16 + i * 4, pa[i]);
                cvt_store(sm + 2 * TILE_B, sm + 3 * TILE_B, lrow, lhal * 16 + i * 4, pb[i]);
            }
            __syncthreads();
        }
    }
}

// ---------------- GEMM1 fused: h = silu(x@Wg^T) * (x@Wu^T) ------------------
__global__ void __launch_bounds__(256, 1) k_gemm1(const float* __restrict__ X,
                                                  const float* __restrict__ Wall) {
    constexpr int K = H_DIM;
    const int mt = blockIdx.y, nt = blockIdx.x;
    const int expert = g_tile_expert[mt];
    if (expert < 0) return;
    const float* __restrict__ Wb = Wall + (size_t)expert * (2 * I_DIM) * K;

    extern __shared__ __align__(128) char sm[];
    float* stash = (float*)(sm + STAGE_B);

    const int tid = threadIdx.x, lane = tid & 31, wid = tid >> 5;
    const int wm = wid & 1, wn = wid >> 1;
    const int lrow = tid >> 1, lhal = tid & 1;

    int tok = g_slot_token[mt * BM + lrow];
    const float* arow = (tok >= 0) ? (X + (size_t)tok * K) : (const float*)0;
    const float* browG = Wb + (size_t)(nt * BN + lrow) * K;
    const float* browU = Wb + (size_t)(I_DIM + nt * BN + lrow) * K;

    const uint32_t uBase = smem_u32(sm);
    float acc[4][4][4];

    // pass 0: gate
    #pragma unroll
    for (int i = 0; i < 4; i++)
        #pragma unroll
        for (int j = 0; j < 4; j++)
            #pragma unroll
            for (int q = 0; q < 4; q++) acc[i][j][q] = 0.f;
    gemm_pass<K>(arow, browG, sm, uBase, lrow, lhal, wm, wn, lane, acc);
    {   // stash gate accumulators (per-thread private region; no sync needed)
        float* st = stash + tid * 64;
        #pragma unroll
        for (int i = 0; i < 4; i++)
            #pragma unroll
            for (int j = 0; j < 4; j++)
                #pragma unroll
                for (int q = 0; q < 4; q++) st[(i * 4 + j) * 4 + q] = acc[i][j][q];
    }

    // pass 1: up
    #pragma unroll
    for (int i = 0; i < 4; i++)
        #pragma unroll
        for (int j = 0; j < 4; j++)
            #pragma unroll
            for (int q = 0; q < 4; q++) acc[i][j][q] = 0.f;
    gemm_pass<K>(arow, browU, sm, uBase, lrow, lhal, wm, wn, lane, acc);

    // epilogue: h = silu(gate) * up -> g_h
    const int mrow = mt * BM + wm * 64;
    const int ncol = nt * BN + wn * 32;
    const float* st = stash + tid * 64;
    #pragma unroll
    for (int i = 0; i < 4; i++) {
        int r0 = mrow + i * 16 + (lane >> 2);
        #pragma unroll
        for (int j = 0; j < 4; j++) {
            int c0 = ncol + j * 8 + 2 * (lane & 3);
            float g0 = st[(i * 4 + j) * 4 + 0], g1 = st[(i * 4 + j) * 4 + 1];
            float g2 = st[(i * 4 + j) * 4 + 2], g3 = st[(i * 4 + j) * 4 + 3];
            float* p0 = g_h + (size_t)r0 * I_DIM + c0;
            p0[0] = g0 / (1.f + __expf(-g0)) * acc[i][j][0];
            p0[1] = g1 / (1.f + __expf(-g1)) * acc[i][j][1];
            float* p1 = p0 + (size_t)8 * I_DIM;
            p1[0] = g2 / (1.f + __expf(-g2)) * acc[i][j][2];
            p1[1] = g3 / (1.f + __expf(-g3)) * acc[i][j][3];
        }
    }
}

// ---------------- GEMM2: y = h @ w2s[e]^T -----------------------------------
__global__ void __launch_bounds__(256, 1) k_gemm2(const float* __restrict__ Wall) {
    constexpr int K = I_DIM;
    const int mt = blockIdx.y, nt = blockIdx.x;
    const int expert = g_tile_expert[mt];
    if (expert < 0) return;
    const float* __restrict__ Wb = Wall + (size_t)expert * H_DIM * K;

    __shared__ __align__(128) char sm[STAGE_B];

    const int tid = threadIdx.x, lane = tid & 31, wid = tid >> 5;
    const int wm = wid & 1, wn = wid >> 1;
    const int lrow = tid >> 1, lhal = tid & 1;

    const float* arow = g_h + (size_t)(mt * BM + lrow) * K;
    const float* brow = Wb + (size_t)(nt * BN + lrow) * K;

    const uint32_t uBase = smem_u32(sm);
    float acc[4][4][4];
    #pragma unroll
    for (int i = 0; i < 4; i++)
        #pragma unroll
        for (int j = 0; j < 4; j++)
            #pragma unroll
            for (int q = 0; q < 4; q++) acc[i][j][q] = 0.f;
    gemm_pass<K>(arow, brow, sm, uBase, lrow, lhal, wm, wn, lane, acc);

    const int mrow = mt * BM + wm * 64;
    const int ncol = nt * BN + wn * 32;
    #pragma unroll
    for (int i = 0; i < 4; i++) {
        int r0 = mrow + i * 16 + (lane >> 2);
        #pragma unroll
        for (int j = 0; j < 4; j++) {
            int c0 = ncol + j * 8 + 2 * (lane & 3);
            float* p0 = g_y + (size_t)r0 * H_DIM + c0;
            p0[0] = acc[i][j][0];
            p0[1] = acc[i][j][1];
            float* p1 = p0 + (size_t)8 * H_DIM;
            p1[0] = acc[i][j][2];
            p1[1] = acc[i][j][3];
        }
    }
}

// ---------------- combine ---------------------------------------------------
__global__ void k_combine(float* __restrict__ out) {
    int idx = blockIdx.x * blockDim.x + threadIdx.x;
    if (idx >= T_TOK * (H_DIM / 4)) return;
    int t = idx / (H_DIM / 4);
    int n = (idx % (H_DIM / 4)) * 4;
    int   s0 = g_tok_slot[t * 2 + 0], s1 = g_tok_slot[t * 2 + 1];
    float w0 = g_tok_w [t * 2 + 0], w1 = g_tok_w [t * 2 + 1];
    const float4 y0 = *(const float4*)&g_y[(size_t)s0 * H_DIM + n];
    const float4 y1 = *(const float4*)&g_y[(size_t)s1 * H_DIM + n];
    float4 o;
    o.x = w0 * y0.x + w1 * y1.x;
    o.y = w0 * y0.y + w1 * y1.y;
    o.z = w0 * y0.z + w1 * y1.z;
    o.w = w0 * y0.w + w1 * y1.w;
    *(float4*)&out[(size_t)t * H_DIM + n] = o;
}

// ---------------- launch ----------------------------------------------------
extern "C" void kernel_launch(void* const* d_in, const int* in_sizes, int n_in,
                              void* d_out, int out_size) {
    const float* x      = (const float*)d_in[0];
    const float* gate_w = (const float*)d_in[1];
    const float* ws     = (const float*)d_in[2];
    const float* w2s    = (const float*)d_in[3];
    float* out = (float*)d_out;

    cudaFuncSetAttribute(k_gemm1, cudaFuncAttributeMaxDynamicSharedMemorySize, DYN1);

    k_init<<<(MAX_SLOTS + 255) / 256, 256>>>();
    k_route<<<T_TOK, 512>>>(x, gate_w);
    k_offsets<<<1, 32>>>();
    k_scatter<<<(T_TOK + 255) / 256, 256>>>();

    k_gemm1<<<dim3(I_DIM / BN, M_TILES), 256, DYN1>>>(x, ws);
    k_gemm2<<<dim3(H_DIM / BN, M_TILES), 256>>>(w2s);
    k_combine<<<(T_TOK * (H_DIM / 4) + 255) / 256, 256>>>(out);
}

// round 8
// speedup vs baseline: 1.0875x; 1.0061x over previous
#include <cuda_runtime.h>
#include <cuda_bf16.h>
#include <math.h>
#include <stdint.h>

#define T_TOK 4096
#define H_DIM 2048
#define I_DIM 2048
#define E_NUM 16

#define BM 128
#define BN 128
#define KC 32
#define PITCH 80                      // bytes per smem row (32 bf16 + pad)
#define TILE_B (BM * PITCH)           // 10240
#define STAGE_B (4 * TILE_B)          // Ahi|Alo|Bhi|Blo = 40960
#define STASH_B (256 * 64 * 4)        // 65536 (per-thread gate stash)
#define DYN1 (STAGE_B + STASH_B)      // 106496

#define MAX_SLOTS (T_TOK * 2 + E_NUM * BM)   // 10240
#define M_TILES   (MAX_SLOTS / BM)           // 80

// ---------------- scratch ---------------------------------------------------
__device__ int   g_slot_token[MAX_SLOTS];
__device__ int   g_tile_expert[M_TILES];
__device__ int   g_counts[E_NUM];
__device__ int   g_cursor[E_NUM];
__device__ int   g_seg_start[E_NUM];
__device__ int   g_tok_eid[T_TOK * 2];
__device__ int   g_tok_slot[T_TOK * 2];
__device__ float g_tok_w[T_TOK * 2];

__device__ float g_h[(size_t)MAX_SLOTS * I_DIM];
__device__ float g_y[(size_t)MAX_SLOTS * H_DIM];

// ---------------- helpers ---------------------------------------------------
__device__ __forceinline__ uint32_t smem_u32(const void* p) {
    uint32_t a;
    asm("{ .reg .u64 t; cvta.to.shared.u64 t, %1; cvt.u32.u64 %0, t; }" : "=r"(a) : "l"(p));
    return a;
}

#define LDSM4(R, A)                                                             \
    asm volatile("ldmatrix.sync.aligned.m8n8.x4.shared.b16 {%0,%1,%2,%3}, [%4];" \
        : "=r"((R)[0]), "=r"((R)[1]), "=r"((R)[2]), "=r"((R)[3]) : "r"(A))

__device__ __forceinline__ void mma_bf16(float* d, const uint32_t* a, const uint32_t* b) {
    asm volatile("mma.sync.aligned.m16n8k16.row.col.f32.bf16.bf16.f32 "
        "{%0,%1,%2,%3}, {%4,%5,%6,%7}, {%8,%9}, {%0,%1,%2,%3};"
        : "+f"(d[0]), "+f"(d[1]), "+f"(d[2]), "+f"(d[3])
        : "r"(a[0]), "r"(a[1]), "r"(a[2]), "r"(a[3]), "r"(b[0]), "r"(b[1]));
}

__device__ __forceinline__ void cvt_store(char* hi_t, char* lo_t, int row, int colf, float4 v) {
    __nv_bfloat162 h01 = __floats2bfloat162_rn(v.x, v.y);
    __nv_bfloat162 h23 = __floats2bfloat162_rn(v.z, v.w);
    float rx = v.x - __bfloat162float(h01.x);
    float ry = v.y - __bfloat162float(h01.y);
    float rz = v.z - __bfloat162float(h23.x);
    float rw = v.w - __bfloat162float(h23.y);
    __nv_bfloat162 l01 = __floats2bfloat162_rn(rx, ry);
    __nv_bfloat162 l23 = __floats2bfloat162_rn(rz, rw);
    uint32_t off = (uint32_t)(row * PITCH + colf * 2);
    *(uint2*)(hi_t + off) = make_uint2(*reinterpret_cast<uint32_t*>(&h01),
                                       *reinterpret_cast<uint32_t*>(&h23));
    *(uint2*)(lo_t + off) = make_uint2(*reinterpret_cast<uint32_t*>(&l01),
                                       *reinterpret_cast<uint32_t*>(&l23));
}

// ---------------- routing / bookkeeping -------------------------------------
__global__ void k_init() {
    int i = blockIdx.x * blockDim.x + threadIdx.x;
    if (i < MAX_SLOTS) g_slot_token[i] = -1;
    if (i < E_NUM) { g_counts[i] = 0; g_cursor[i] = 0; }
}

__global__ void __launch_bounds__(512) k_route(const float* __restrict__ x,
                                               const float* __restrict__ gw) {
    int t = blockIdx.x, warp = threadIdx.x >> 5, lane = threadIdx.x & 31;
    const float* xr = x + (size_t)t * H_DIM;
    const float* gr = gw + (size_t)warp * H_DIM;
    float s = 0.f;
    for (int k = lane; k < H_DIM; k += 32) s += xr[k] * gr[k];
    #pragma unroll
    for (int o = 16; o; o >>= 1) s += __shfl_xor_sync(0xffffffffu, s, o);
    __shared__ float logits[E_NUM];
    if (lane == 0) logits[warp] = s;
    __syncthreads();
    if (threadIdx.x == 0) {
        int i0 = -1, i1 = -1; float v0 = -1e30f, v1 = -1e30f;
        #pragma unroll
        for (int e = 0; e < E_NUM; e++) {
            float v = logits[e];
            if (v > v0) { v1 = v0; i1 = i0; v0 = v; i0 = e; }
            else if (v > v1) { v1 = v; i1 = e; }
        }
        float e1 = expf(v1 - v0);
        float w0 = 1.f / (1.f + e1);
        g_tok_eid[t * 2 + 0] = i0;  g_tok_eid[t * 2 + 1] = i1;
        g_tok_w [t * 2 + 0] = w0;  g_tok_w [t * 2 + 1] = e1 * w0;
        atomicAdd(&g_counts[i0], 1);
        atomicAdd(&g_counts[i1], 1);
    }
}

__global__ void k_offsets() {
    if (threadIdx.x == 0 && blockIdx.x == 0) {
        int run = 0;
        for (int e = 0; e < E_NUM; e++) {
            g_seg_start[e] = run;
            int padded = (g_counts[e] + BM - 1) / BM * BM;
            for (int tt = run / BM; tt < (run + padded) / BM; tt++) g_tile_expert[tt] = e;
            run += padded;
        }
        for (int tt = run / BM; tt < M_TILES; tt++) g_tile_expert[tt] = -1;  // dead tiles
    }
}

__global__ void k_scatter() {
    int t = blockIdx.x * blockDim.x + threadIdx.x;
    if (t >= T_TOK) return;
    #pragma unroll
    for (int k = 0; k < 2; k++) {
        int e = g_tok_eid[t * 2 + k];
        int pos = atomicAdd(&g_cursor[e], 1);
        int slot = g_seg_start[e] + pos;
        g_slot_token[slot] = t;
        g_tok_slot[t * 2 + k] = slot;
    }
}

// ---------------- shared mainloop: one K-pass of 128x128 bf16-split ---------
template <int K>
__device__ __forceinline__ void gemm_pass(const float* arow, const float* brow,
                                          char* sm, uint32_t uBase,
                                          int lrow, int lhal, int wm, int wn, int lane,
                                          float acc[4][4][4]) {
    constexpr int NCH = K / KC;
    float4 pa[4], pb[4];
    #pragma unroll
    for (int i = 0; i < 4; i++) {
        pa[i] = arow ? *(const float4*)(arow + lhal * 16 + i * 4)
                     : make_float4(0.f, 0.f, 0.f, 0.f);
        pb[i] = *(const float4*)(brow + lhal * 16 + i * 4);
    }
    #pragma unroll
    for (int i = 0; i < 4; i++) {
        cvt_store(sm,              sm + TILE_B,     lrow, lhal * 16 + i * 4, pa[i]);
        cvt_store(sm + 2 * TILE_B, sm + 3 * TILE_B, lrow, lhal * 16 + i * 4, pb[i]);
    }
    __syncthreads();

    for (int ic = 0; ic < NCH; ic++) {
        if (ic + 1 < NCH) {
            const int kb = (ic + 1) * KC;
            #pragma unroll
            for (int i = 0; i < 4; i++) {
                pa[i] = arow ? *(const float4*)(arow + kb + lhal * 16 + i * 4)
                             : make_float4(0.f, 0.f, 0.f, 0.f);
                pb[i] = *(const float4*)(brow + kb + lhal * 16 + i * 4);
            }
        }
        #pragma unroll
        for (int k16 = 0; k16 < 2; k16++) {
            uint32_t ahi[4][4], alo[4][4];
            #pragma unroll
            for (int i = 0; i < 4; i++) {
                uint32_t ad = uBase + (uint32_t)((wm * 64 + i * 16 + (lane & 15)) * PITCH
                                                 + k16 * 32 + (lane >> 4) * 16);
                LDSM4(ahi[i], ad);
                LDSM4(alo[i], ad + TILE_B);
            }
            uint32_t bhi[8], blo[8];
            #pragma unroll
            for (int p = 0; p < 2; p++) {
                uint32_t bd = uBase + (uint32_t)(2 * TILE_B)
                            + (uint32_t)((wn * 32 + p * 16 + (lane & 7) + ((lane >> 4) << 3)) * PITCH
                                         + k16 * 32 + ((lane >> 3) & 1) * 16);
                LDSM4(&bhi[p * 4], bd);
                LDSM4(&blo[p * 4], bd + TILE_B);
            }
            #pragma unroll
            for (int i = 0; i < 4; i++)
                #pragma unroll
                for (int j = 0; j < 4; j++) {
                    const uint32_t* bh = &bhi[(j >> 1) * 4 + (j & 1) * 2];
                    const uint32_t* bl = &blo[(j >> 1) * 4 + (j & 1) * 2];
                    mma_bf16(acc[i][j], ahi[i], bh);
                    mma_bf16(acc[i][j], ahi[i], bl);
                    mma_bf16(acc[i][j], alo[i], bh);
                }
        }
        __syncthreads();
        if (ic + 1 < NCH) {
            #pragma unroll
            for (int i = 0; i < 4; i++) {
                cvt_store(sm,              sm + TILE_B,     lrow, lhal * 16 + i * 4, pa[i]);
                cvt_store(sm + 2 * TILE_B, sm + 3 * TILE_B, lrow, lhal * 16 + i * 4, pb[i]);
            }
            __syncthreads();
        }
    }
}

// ---------------- GEMM1 fused: h = silu(x@Wg^T) * (x@Wu^T) ------------------
__global__ void __launch_bounds__(256, 1) k_gemm1(const float* __restrict__ X,
                                                  const float* __restrict__ Wall) {
    constexpr int K = H_DIM;
    const int mt = blockIdx.y, nt = blockIdx.x;
    const int expert = g_tile_expert[mt];
    if (expert < 0) return;
    const float* __restrict__ Wb = Wall + (size_t)expert * (2 * I_DIM) * K;

    extern __shared__ __align__(128) char sm[];
    float* stash = (float*)(sm + STAGE_B);

    const int tid = threadIdx.x, lane = tid & 31, wid = tid >> 5;
    const int wm = wid & 1, wn = wid >> 1;
    const int lrow = tid >> 1, lhal = tid & 1;

    int tok = g_slot_token[mt * BM + lrow];
    const float* arow = (tok >= 0) ? (X + (size_t)tok * K) : (const float*)0;
    const float* browG = Wb + (size_t)(nt * BN + lrow) * K;
    const float* browU = Wb + (size_t)(I_DIM + nt * BN + lrow) * K;

    const uint32_t uBase = smem_u32(sm);
    float acc[4][4][4];

    // pass 0: gate
    #pragma unroll
    for (int i = 0; i < 4; i++)
        #pragma unroll
        for (int j = 0; j < 4; j++)
            #pragma unroll
            for (int q = 0; q < 4; q++) acc[i][j][q] = 0.f;
    gemm_pass<K>(arow, browG, sm, uBase, lrow, lhal, wm, wn, lane, acc);
    {   // stash gate accumulators (per-thread private region; no sync needed)
        float* st = stash + tid * 64;
        #pragma unroll
        for (int i = 0; i < 4; i++)
            #pragma unroll
            for (int j = 0; j < 4; j++)
                #pragma unroll
                for (int q = 0; q < 4; q++) st[(i * 4 + j) * 4 + q] = acc[i][j][q];
    }

    // pass 1: up
    #pragma unroll
    for (int i = 0; i < 4; i++)
        #pragma unroll
        for (int j = 0; j < 4; j++)
            #pragma unroll
            for (int q = 0; q < 4; q++) acc[i][j][q] = 0.f;
    gemm_pass<K>(arow, browU, sm, uBase, lrow, lhal, wm, wn, lane, acc);

    // epilogue: h = silu(gate) * up -> g_h
    const int mrow = mt * BM + wm * 64;
    const int ncol = nt * BN + wn * 32;
    const float* st = stash + tid * 64;
    #pragma unroll
    for (int i = 0; i < 4; i++) {
        int r0 = mrow + i * 16 + (lane >> 2);
        #pragma unroll
        for (int j = 0; j < 4; j++) {
            int c0 = ncol + j * 8 + 2 * (lane & 3);
            float g0 = st[(i * 4 + j) * 4 + 0], g1 = st[(i * 4 + j) * 4 + 1];
            float g2 = st[(i * 4 + j) * 4 + 2], g3 = st[(i * 4 + j) * 4 + 3];
            float* p0 = g_h + (size_t)r0 * I_DIM + c0;
            p0[0] = g0 / (1.f + __expf(-g0)) * acc[i][j][0];
            p0[1] = g1 / (1.f + __expf(-g1)) * acc[i][j][1];
            float* p1 = p0 + (size_t)8 * I_DIM;
            p1[0] = g2 / (1.f + __expf(-g2)) * acc[i][j][2];
            p1[1] = g3 / (1.f + __expf(-g3)) * acc[i][j][3];
        }
    }
}

// ---------------- GEMM2: y = h @ w2s[e]^T -----------------------------------
__global__ void __launch_bounds__(256, 1) k_gemm2(const float* __restrict__ Wall) {
    constexpr int K = I_DIM;
    const int mt = blockIdx.y, nt = blockIdx.x;
    const int expert = g_tile_expert[mt];
    if (expert < 0) return;
    const float* __restrict__ Wb = Wall + (size_t)expert * H_DIM * K;

    __shared__ __align__(128) char sm[STAGE_B];

    const int tid = threadIdx.x, lane = tid & 31, wid = tid >> 5;
    const int wm = wid & 1, wn = wid >> 1;
    const int lrow = tid >> 1, lhal = tid & 1;

    const float* arow = g_h + (size_t)(mt * BM + lrow) * K;
    const float* brow = Wb + (size_t)(nt * BN + lrow) * K;

    const uint32_t uBase = smem_u32(sm);
    float acc[4][4][4];
    #pragma unroll
    for (int i = 0; i < 4; i++)
        #pragma unroll
        for (int j = 0; j < 4; j++)
            #pragma unroll
            for (int q = 0; q < 4; q++) acc[i][j][q] = 0.f;
    gemm_pass<K>(arow, brow, sm, uBase, lrow, lhal, wm, wn, lane, acc);

    const int mrow = mt * BM + wm * 64;
    const int ncol = nt * BN + wn * 32;
    #pragma unroll
    for (int i = 0; i < 4; i++) {
        int r0 = mrow + i * 16 + (lane >> 2);
        #pragma unroll
        for (int j = 0; j < 4; j++) {
            int c0 = ncol + j * 8 + 2 * (lane & 3);
            float* p0 = g_y + (size_t)r0 * H_DIM + c0;
            p0[0] = acc[i][j][0];
            p0[1] = acc[i][j][1];
            float* p1 = p0 + (size_t)8 * H_DIM;
            p1[0] = acc[i][j][2];
            p1[1] = acc[i][j][3];
        }
    }
}

// ---------------- combine ---------------------------------------------------
__global__ void k_combine(float* __restrict__ out) {
    int idx = blockIdx.x * blockDim.x + threadIdx.x;
    if (idx >= T_TOK * (H_DIM / 4)) return;
    int t = idx / (H_DIM / 4);
    int n = (idx % (H_DIM / 4)) * 4;
    int   s0 = g_tok_slot[t * 2 + 0], s1 = g_tok_slot[t * 2 + 1];
    float w0 = g_tok_w [t * 2 + 0], w1 = g_tok_w [t * 2 + 1];
    const float4 y0 = *(const float4*)&g_y[(size_t)s0 * H_DIM + n];
    const float4 y1 = *(const float4*)&g_y[(size_t)s1 * H_DIM + n];
    float4 o;
    o.x = w0 * y0.x + w1 * y1.x;
    o.y = w0 * y0.y + w1 * y1.y;
    o.z = w0 * y0.z + w1 * y1.z;
    o.w = w0 * y0.w + w1 * y1.w;
    *(float4*)&out[(size_t)t * H_DIM + n] = o;
}

// ---------------- launch ----------------------------------------------------
extern "C" void kernel_launch(void* const* d_in, const int* in_sizes, int n_in,
                              void* d_out, int out_size) {
    const float* x      = (const float*)d_in[0];
    const float* gate_w = (const float*)d_in[1];
    const float* ws     = (const float*)d_in[2];
    const float* w2s    = (const float*)d_in[3];
    float* out = (float*)d_out;

    cudaFuncSetAttribute(k_gemm1, cudaFuncAttributeMaxDynamicSharedMemorySize, DYN1);

    k_init<<<(MAX_SLOTS + 255) / 256, 256>>>();
    k_route<<<T_TOK, 512>>>(x, gate_w);
    k_offsets<<<1, 32>>>();
    k_scatter<<<(T_TOK + 255) / 256, 256>>>();

    k_gemm1<<<dim3(I_DIM / BN, M_TILES), 256, DYN1>>>(x, ws);
    k_gemm2<<<dim3(H_DIM / BN, M_TILES), 256>>>(w2s);
    k_combine<<<(T_TOK * (H_DIM / 4) + 255) / 256, 256>>>(out);
}